// round 1
// baseline (speedup 1.0000x reference)
#include <cuda_runtime.h>
#include <math.h>

#define SEQ   512
#define BATCH 64
#define DIM   512
#define HID   1024
#define GATES 4096   // 4*HID

// Scratch (allocation-free rule: __device__ globals)
__device__ float g_gx[(size_t)SEQ * BATCH * GATES];   // 512 MB precomputed input projection
__device__ float g_h[2][BATCH * HID];                 // ping-pong hidden state
__device__ float g_c[BATCH * HID];                    // cell state (in-place)

// ---------------------------------------------------------------------------
// Copy initial state into device globals
// ---------------------------------------------------------------------------
__global__ void init_state(const float* __restrict__ h0, const float* __restrict__ c0) {
    int i = blockIdx.x * blockDim.x + threadIdx.x;
    if (i < BATCH * HID) {
        g_h[0][i] = h0[i];
        g_h[1][i] = 0.0f;
        g_c[i]    = c0[i];
    }
}

// ---------------------------------------------------------------------------
// gx = x @ Wx   : (32768 x 4096), K = 512. Tiled fp32 SGEMM.
// Block tile 64x64, 256 threads, 4x4 micro-tile per thread, KT = 16.
// ---------------------------------------------------------------------------
__global__ void gx_gemm(const float* __restrict__ x, const float* __restrict__ Wx) {
    __shared__ float shA[64][17];   // [row][k] padded
    __shared__ float shB[16][68];   // [k][col] padded (68 floats = 272B, 16B-aligned rows)

    const int bm = blockIdx.y * 64;
    const int bn = blockIdx.x * 64;
    const int tid = threadIdx.x;            // 256
    const int tx = tid & 15;                // col group
    const int ty = tid >> 4;                // row group

    float acc[4][4] = {};

    for (int k0 = 0; k0 < DIM; k0 += 16) {
        // load A tile: 64x16 floats, one float4 per thread
        {
            int r = tid >> 2, v = tid & 3;
            float4 fa = *reinterpret_cast<const float4*>(x + (size_t)(bm + r) * DIM + k0 + v * 4);
            shA[r][v * 4 + 0] = fa.x;
            shA[r][v * 4 + 1] = fa.y;
            shA[r][v * 4 + 2] = fa.z;
            shA[r][v * 4 + 3] = fa.w;
        }
        // load B tile: 16x64 floats, one float4 per thread
        {
            int kk = tid >> 4, v = tid & 15;
            float4 fb = *reinterpret_cast<const float4*>(Wx + (size_t)(k0 + kk) * GATES + bn + v * 4);
            *reinterpret_cast<float4*>(&shB[kk][v * 4]) = fb;
        }
        __syncthreads();

        #pragma unroll
        for (int kk = 0; kk < 16; kk++) {
            float a[4];
            #pragma unroll
            for (int i = 0; i < 4; i++) a[i] = shA[ty * 4 + i][kk];
            float4 b4 = *reinterpret_cast<const float4*>(&shB[kk][tx * 4]);
            #pragma unroll
            for (int i = 0; i < 4; i++) {
                acc[i][0] = fmaf(a[i], b4.x, acc[i][0]);
                acc[i][1] = fmaf(a[i], b4.y, acc[i][1]);
                acc[i][2] = fmaf(a[i], b4.z, acc[i][2]);
                acc[i][3] = fmaf(a[i], b4.w, acc[i][3]);
            }
        }
        __syncthreads();
    }

    #pragma unroll
    for (int i = 0; i < 4; i++) {
        float4 v = make_float4(acc[i][0], acc[i][1], acc[i][2], acc[i][3]);
        *reinterpret_cast<float4*>(&g_gx[(size_t)(bm + ty * 4 + i) * GATES + bn + tx * 4]) = v;
    }
}

// ---------------------------------------------------------------------------
// One LSTM step, fully fused: gates = gx[t] + h @ Wh + bh, then cell update.
// Grid: 128 blocks; block hb owns hidden indices [hb*8, hb*8+8) and computes
// the 4 gate columns (i/f/j/o) for those indices across all 64 batch rows.
// GEMM: 64x32 output, K=1024, KT=32, 256 threads, 8 rows x 1 col per thread.
// ---------------------------------------------------------------------------
__global__ void lstm_step(const float* __restrict__ Wh, const float* __restrict__ bh, int t) {
    __shared__ float shH [64][36];   // [row][k]   (36 floats = 144B rows, 16B-aligned)
    __shared__ float shWT[32][36];   // [col][k]   transposed for float4 K-reads
    __shared__ float shG [64][33];   // staged gates for elementwise

    const float* __restrict__ h_in  = g_h[t & 1];
    float*       __restrict__ h_out = g_h[(t + 1) & 1];
    const float* __restrict__ gx_t  = g_gx + (size_t)t * BATCH * GATES;

    const int tid  = threadIdx.x;     // 256
    const int col  = tid & 31;        // output column within 64x32 tile
    const int rg   = tid >> 5;        // row group 0..7 (8 rows each)
    const int hb   = blockIdx.x;      // hidden strip
    const int gate = col >> 3;
    const int idx  = col & 7;
    const int gcol = gate * HID + hb * 8 + idx;   // column in the 4096-wide gate matrix

    float acc[8];
    {
        const float bias = bh[gcol];
        #pragma unroll
        for (int r = 0; r < 8; r++)
            acc[r] = gx_t[(rg * 8 + r) * GATES + gcol] + bias;
    }

    for (int k0 = 0; k0 < HID; k0 += 32) {
        // load h tile: 64x32 floats = 512 float4, 2 per thread, coalesced
        #pragma unroll
        for (int q = 0; q < 2; q++) {
            int e = tid * 2 + q;           // 0..511
            int r = e >> 3, v = e & 7;
            float4 f = *reinterpret_cast<const float4*>(h_in + r * HID + k0 + v * 4);
            *reinterpret_cast<float4*>(&shH[r][v * 4]) = f;
        }
        // load Wh tile transposed: each thread fills its own column's k-entries
        #pragma unroll
        for (int q = 0; q < 4; q++) {
            int kk = (tid >> 5) + q * 8;   // 0..31
            shWT[col][kk] = Wh[(size_t)(k0 + kk) * GATES + gcol];
        }
        __syncthreads();

        #pragma unroll
        for (int kk = 0; kk < 32; kk += 4) {
            float4 w = *reinterpret_cast<const float4*>(&shWT[col][kk]);
            #pragma unroll
            for (int r = 0; r < 8; r++) {
                float4 a = *reinterpret_cast<const float4*>(&shH[rg * 8 + r][kk]);
                acc[r] = fmaf(a.x, w.x, acc[r]);
                acc[r] = fmaf(a.y, w.y, acc[r]);
                acc[r] = fmaf(a.z, w.z, acc[r]);
                acc[r] = fmaf(a.w, w.w, acc[r]);
            }
        }
        __syncthreads();
    }

    // stage gates, then fused elementwise cell update
    #pragma unroll
    for (int r = 0; r < 8; r++) shG[rg * 8 + r][col] = acc[r];
    __syncthreads();

    #pragma unroll
    for (int q = 0; q < 2; q++) {
        int e  = tid + q * 256;            // 0..511 = 64 batch x 8 hidx
        int b  = e >> 3, ix = e & 7;
        float gi = shG[b][ix];
        float gf = shG[b][8  + ix];
        float gj = shG[b][16 + ix];
        float go = shG[b][24 + ix];
        int   ci = b * HID + hb * 8 + ix;

        float si = 1.0f / (1.0f + expf(-gi));
        float sf = 1.0f / (1.0f + expf(-(gf + 1.0f)));   // FORGET_BIAS = 1.0
        float so = 1.0f / (1.0f + expf(-go));
        float cn = g_c[ci] * sf + si * tanhf(gj);
        g_c[ci]   = cn;
        h_out[ci] = tanhf(cn) * so;
    }
}

// ---------------------------------------------------------------------------
// Final state -> output buffer: [h (64x1024), c (64x1024)]
// ---------------------------------------------------------------------------
__global__ void write_out(float* __restrict__ out) {
    int i = blockIdx.x * blockDim.x + threadIdx.x;
    if (i < BATCH * HID) {
        out[i]               = g_h[0][i];   // after 512 steps, final h is in buffer 0
        out[BATCH * HID + i] = g_c[i];
    }
}

// ---------------------------------------------------------------------------
extern "C" void kernel_launch(void* const* d_in, const int* in_sizes, int n_in,
                              void* d_out, int out_size) {
    const float* x  = (const float*)d_in[0];
    const float* h0 = (const float*)d_in[1];
    const float* c0 = (const float*)d_in[2];
    const float* Wx = (const float*)d_in[3];
    const float* Wh = (const float*)d_in[4];
    const float* bh = (const float*)d_in[5];
    float* out = (float*)d_out;

    init_state<<<64, 1024>>>(h0, c0);
    gx_gemm<<<dim3(GATES / 64, (SEQ * BATCH) / 64), 256>>>(x, Wx);
    for (int t = 0; t < SEQ; t++)
        lstm_step<<<128, 256>>>(Wh, bh, t);
    write_out<<<64, 1024>>>(out);
}

// round 5
// speedup vs baseline: 2.3328x; 2.3328x over previous
#include <cuda_runtime.h>
#include <cuda_bf16.h>
#include <math.h>
#include <stdint.h>

#define SEQ    512
#define BATCH  64
#define DIM    512
#define HID    1024
#define GATES  4096
#define NCTA   128
#define NTHR   256

// ---------------------------------------------------------------------------
// Device scratch (allocation-free rule)
// ---------------------------------------------------------------------------
__device__ float          g_gx[(size_t)SEQ * BATCH * GATES];   // input projection
__device__ __nv_bfloat16  g_wt_hi[(size_t)GATES * HID];        // WhT split hi, [n][k]
__device__ __nv_bfloat16  g_wt_lo[(size_t)GATES * HID];        // WhT split lo
__device__ __nv_bfloat16  g_h_hi[2][BATCH * HID];              // ping-pong hidden, hi
__device__ __nv_bfloat16  g_h_lo[2][BATCH * HID];              // ping-pong hidden, lo
__device__ unsigned       g_bar_cnt;
__device__ unsigned       g_bar_gen;

// ---------------------------------------------------------------------------
// PTX helpers (portable sm_80+ tensor path: ldmatrix + mma.sync + cp.async)
// ---------------------------------------------------------------------------
__device__ __forceinline__ uint32_t smem_u32(const void* p) {
    uint32_t a;
    asm("{ .reg .u64 t; cvta.to.shared.u64 t, %1; cvt.u32.u64 %0, t; }" : "=r"(a) : "l"(p));
    return a;
}

#define LDSM_X4(r0, r1, r2, r3, addr) \
    asm volatile("ldmatrix.sync.aligned.m8n8.x4.shared.b16 {%0,%1,%2,%3}, [%4];" \
                 : "=r"(r0), "=r"(r1), "=r"(r2), "=r"(r3) : "r"(addr))

#define MMA16816(c, a0, a1, a2, a3, b0, b1) \
    asm volatile("mma.sync.aligned.m16n8k16.row.col.f32.bf16.bf16.f32 " \
                 "{%0,%1,%2,%3}, {%4,%5,%6,%7}, {%8,%9}, {%0,%1,%2,%3};" \
                 : "+f"((c)[0]), "+f"((c)[1]), "+f"((c)[2]), "+f"((c)[3]) \
                 : "r"(a0), "r"(a1), "r"(a2), "r"(a3), "r"(b0), "r"(b1))

__device__ __forceinline__ void cpa16(uint32_t dst, const void* src) {
    asm volatile("cp.async.cg.shared.global [%0], [%1], 16;" :: "r"(dst), "l"(src));
}
#define CPA_COMMIT() asm volatile("cp.async.commit_group;" ::: "memory")
#define CPA_WAIT(n)  asm volatile("cp.async.wait_group %0;" :: "n"(n) : "memory")

// ---------------------------------------------------------------------------
// SMEM layout (byte offsets from dynamic smem base)
//   B rows padded to 2064 B (1024 bf16 + 8), A rows padded to 272 B (128 bf16 + 8)
//   -> conflict-free ldmatrix lane addressing, no swizzle needed.
//   GX rows padded to 144 B (32 floats + 4) -> 16B-aligned cp.async dst.
// ---------------------------------------------------------------------------
#define BSTR     2064u
#define ASTR     272u
#define SM_BHI   0u                              // 32 * 2064 = 66048
#define SM_BLO   66048u                          // 66048
#define SM_A     132096u                         // 2 stages * (hi 17408 + lo 17408)
#define A_STAGE  34816u
#define A_LO     17408u
#define SM_GX    201728u                         // 64 rows * 144 B = 9216
#define GXSTR    144u
#define SM_SG    210944u                         // 64 rows * 136 B = 8704
#define SM_BIAS  219648u                         // 32 floats
#define SM_TOTAL 219776u

// ---------------------------------------------------------------------------
// Init kernels
// ---------------------------------------------------------------------------
__global__ void split_wh(const float* __restrict__ Wh) {
    int n = blockIdx.x;  // gate column 0..4095
    for (int k = threadIdx.x; k < HID; k += blockDim.x) {
        float w = Wh[(size_t)k * GATES + n];
        __nv_bfloat16 hh = __float2bfloat16(w);
        g_wt_hi[(size_t)n * HID + k] = hh;
        g_wt_lo[(size_t)n * HID + k] = __float2bfloat16(w - __bfloat162float(hh));
    }
}

__global__ void split_h0(const float* __restrict__ h0) {
    int i = blockIdx.x * blockDim.x + threadIdx.x;
    if (i < BATCH * HID) {
        float v = h0[i];
        __nv_bfloat16 hh = __float2bfloat16(v);
        g_h_hi[0][i] = hh;
        g_h_lo[0][i] = __float2bfloat16(v - __bfloat162float(hh));
    }
}

// ---------------------------------------------------------------------------
// gx = x @ Wx : (32768 x 4096), K=512 fp32 tiled SGEMM
// ---------------------------------------------------------------------------
__global__ void gx_gemm(const float* __restrict__ x, const float* __restrict__ Wx) {
    __shared__ float shA[64][17];
    __shared__ float shB[16][68];

    const int bm = blockIdx.y * 64;
    const int bn = blockIdx.x * 64;
    const int tid = threadIdx.x;
    const int tx = tid & 15;
    const int ty = tid >> 4;

    float acc[4][4] = {};

    for (int k0 = 0; k0 < DIM; k0 += 16) {
        {
            int r = tid >> 2, v = tid & 3;
            float4 fa = *reinterpret_cast<const float4*>(x + (size_t)(bm + r) * DIM + k0 + v * 4);
            shA[r][v * 4 + 0] = fa.x; shA[r][v * 4 + 1] = fa.y;
            shA[r][v * 4 + 2] = fa.z; shA[r][v * 4 + 3] = fa.w;
        }
        {
            int kk = tid >> 4, v = tid & 15;
            float4 fb = *reinterpret_cast<const float4*>(Wx + (size_t)(k0 + kk) * GATES + bn + v * 4);
            *reinterpret_cast<float4*>(&shB[kk][v * 4]) = fb;
        }
        __syncthreads();

        #pragma unroll
        for (int kk = 0; kk < 16; kk++) {
            float a[4];
            #pragma unroll
            for (int i = 0; i < 4; i++) a[i] = shA[ty * 4 + i][kk];
            float4 b4 = *reinterpret_cast<const float4*>(&shB[kk][tx * 4]);
            #pragma unroll
            for (int i = 0; i < 4; i++) {
                acc[i][0] = fmaf(a[i], b4.x, acc[i][0]);
                acc[i][1] = fmaf(a[i], b4.y, acc[i][1]);
                acc[i][2] = fmaf(a[i], b4.z, acc[i][2]);
                acc[i][3] = fmaf(a[i], b4.w, acc[i][3]);
            }
        }
        __syncthreads();
    }

    #pragma unroll
    for (int i = 0; i < 4; i++) {
        float4 v = make_float4(acc[i][0], acc[i][1], acc[i][2], acc[i][3]);
        *reinterpret_cast<float4*>(&g_gx[(size_t)(bm + ty * 4 + i) * GATES + bn + tx * 4]) = v;
    }
}

// ---------------------------------------------------------------------------
// Persistent LSTM recurrence: 512 steps, mma.sync bf16 hi/lo (3-pass split).
// CTA hb owns gate cols n=0..31 -> gcol = (n>>3)*HID + hb*8 + (n&7).
// GEMM per step: D[64,32] += h[64,1024] * Wslice[32,1024]^T
// Warp w: m16-tile (w&3), n16-half (w>>2).
// ---------------------------------------------------------------------------
__global__ void __launch_bounds__(NTHR, 1)
lstm_persist(const float* __restrict__ c0, const float* __restrict__ bh,
             float* __restrict__ out) {
    extern __shared__ char sm[];
    const uint32_t sb = smem_u32(sm);

    const int tid = threadIdx.x;
    const int wid = tid >> 5;
    const int lid = tid & 31;
    const int hb  = blockIdx.x;

    // ---- load resident Wh slice [n=0..31][k=0..1023], hi+lo ----
    for (int idx = tid; idx < 32 * 128; idx += NTHR) {
        int n = idx >> 7, u = idx & 127;                       // u = 16B unit along k
        int gr = (n >> 3) * HID + hb * 8 + (n & 7);
        uint32_t dst = n * BSTR + u * 16u;
        *reinterpret_cast<uint4*>(sm + SM_BHI + dst) =
            *reinterpret_cast<const uint4*>(g_wt_hi + (size_t)gr * HID + u * 8);
        *reinterpret_cast<uint4*>(sm + SM_BLO + dst) =
            *reinterpret_cast<const uint4*>(g_wt_lo + (size_t)gr * HID + u * 8);
    }

    // ---- bias ----
    if (tid < 32) {
        int gc = (tid >> 3) * HID + hb * 8 + (tid & 7);
        *reinterpret_cast<float*>(sm + SM_BIAS + tid * 4) = bh[gc];
    }

    // ---- cell state in registers (warps 0,1; row = wid*32+lid) ----
    const int row = wid * 32 + lid;
    float creg[8];
    if (wid < 2) {
        #pragma unroll
        for (int j = 0; j < 8; j++) creg[j] = c0[row * HID + hb * 8 + j];
    }
    __syncthreads();

    // ---- per-warp constant lane offsets ----
    const int mt = wid & 3;           // m16 tile
    const int nh = wid >> 2;          // n16 half
    const uint32_t a_lane = (uint32_t)(mt * 16 + (lid & 15)) * ASTR + (uint32_t)(lid >> 4) * 16u;
    const uint32_t b_lane = (uint32_t)(nh * 16 + (lid & 7) + ((lid >> 4) << 3)) * BSTR
                          + (uint32_t)((lid >> 3) & 1) * 16u;
    const float* bsm = reinterpret_cast<const float*>(sm + SM_BIAS);

    for (int t = 0; t < SEQ; t++) {
        const __nv_bfloat16* hs_hi = g_h_hi[t & 1];
        const __nv_bfloat16* hs_lo = g_h_lo[t & 1];

        // prologue: chunk 0 (k=0..127) + gx tile
        {
            #pragma unroll
            for (int i = 0; i < 4; i++) {
                int e = tid + i * NTHR;                 // 0..1023
                int r = e >> 4, u = e & 15;
                uint32_t dst = SM_A + (uint32_t)r * ASTR + (uint32_t)u * 16u;
                cpa16(sb + dst,        hs_hi + r * HID + u * 8);
                cpa16(sb + dst + A_LO, hs_lo + r * HID + u * 8);
            }
            #pragma unroll
            for (int i = 0; i < 2; i++) {
                int e = tid + i * NTHR;                 // 0..511
                int r = e >> 3, u = e & 7;
                const float* src = g_gx + ((size_t)t * BATCH + r) * GATES
                                 + (u >> 1) * HID + hb * 8 + (u & 1) * 4;
                cpa16(sb + SM_GX + (uint32_t)r * GXSTR + (uint32_t)u * 16u, src);
            }
            CPA_COMMIT();
        }

        float acc[8] = {};   // 2 n8-tiles x 4

        #pragma unroll 1
        for (int c = 0; c < 8; c++) {
            // prefetch next chunk
            if (c < 7) {
                uint32_t stg = SM_A + (uint32_t)((c + 1) & 1) * A_STAGE;
                int kc = (c + 1) * 128;
                #pragma unroll
                for (int i = 0; i < 4; i++) {
                    int e = tid + i * NTHR;
                    int r = e >> 4, u = e & 15;
                    uint32_t dst = stg + (uint32_t)r * ASTR + (uint32_t)u * 16u;
                    cpa16(sb + dst,        hs_hi + r * HID + kc + u * 8);
                    cpa16(sb + dst + A_LO, hs_lo + r * HID + kc + u * 8);
                }
                CPA_COMMIT();
                CPA_WAIT(1);
            } else {
                CPA_WAIT(0);
            }
            __syncthreads();

            const uint32_t a_hi = sb + SM_A + (uint32_t)(c & 1) * A_STAGE + a_lane;
            const uint32_t a_lo = a_hi + A_LO;
            const uint32_t b_hi = sb + SM_BHI + b_lane + (uint32_t)c * 256u;   // chunk k-offset
            const uint32_t b_lo = b_hi + (SM_BLO - SM_BHI);

            #pragma unroll
            for (int kk = 0; kk < 8; kk++) {
                uint32_t ah0, ah1, ah2, ah3, al0, al1, al2, al3;
                uint32_t bh0, bh1, bh2, bh3, bl0, bl1, bl2, bl3;
                LDSM_X4(ah0, ah1, ah2, ah3, a_hi + kk * 32u);
                LDSM_X4(bh0, bh1, bh2, bh3, b_hi + kk * 32u);
                LDSM_X4(al0, al1, al2, al3, a_lo + kk * 32u);
                LDSM_X4(bl0, bl1, bl2, bl3, b_lo + kk * 32u);

                MMA16816(acc,     ah0, ah1, ah2, ah3, bh0, bh1);
                MMA16816(acc + 4, ah0, ah1, ah2, ah3, bh2, bh3);
                MMA16816(acc,     ah0, ah1, ah2, ah3, bl0, bl1);
                MMA16816(acc + 4, ah0, ah1, ah2, ah3, bl2, bl3);
                MMA16816(acc,     al0, al1, al2, al3, bh0, bh1);
                MMA16816(acc + 4, al0, al1, al2, al3, bh2, bh3);
            }
            __syncthreads();   // protect stage before next prefetch overwrites
        }

        // ---- stage gates to SMEM ----
        {
            float* sg = reinterpret_cast<float*>(sm + SM_SG);
            int r0 = mt * 16 + (lid >> 2);
            int cb = nh * 16 + (lid & 3) * 2;
            #pragma unroll
            for (int ng = 0; ng < 2; ng++) {
                float* p0 = sg + (size_t)r0 * 34 + cb + ng * 8;
                float* p1 = sg + (size_t)(r0 + 8) * 34 + cb + ng * 8;
                p0[0] = acc[ng * 4 + 0]; p0[1] = acc[ng * 4 + 1];
                p1[0] = acc[ng * 4 + 2]; p1[1] = acc[ng * 4 + 3];
            }
        }
        __syncthreads();

        // ---- fused elementwise cell update (warps 0,1) ----
        if (wid < 2) {
            const float* sg    = reinterpret_cast<const float*>(sm + SM_SG) + (size_t)row * 34;
            const float* gxrow = reinterpret_cast<const float*>(sm + SM_GX + (uint32_t)row * GXSTR);
            __nv_bfloat16* hd_hi = g_h_hi[(t + 1) & 1];
            __nv_bfloat16* hd_lo = g_h_lo[(t + 1) & 1];

            #pragma unroll
            for (int j = 0; j < 8; j++) {
                float gi = sg[j]      + gxrow[j]      + bsm[j];
                float gf = sg[8 + j]  + gxrow[8 + j]  + bsm[8 + j];
                float gj = sg[16 + j] + gxrow[16 + j] + bsm[16 + j];
                float go = sg[24 + j] + gxrow[24 + j] + bsm[24 + j];

                float si = 1.0f / (1.0f + expf(-gi));
                float sf = 1.0f / (1.0f + expf(-(gf + 1.0f)));   // FORGET_BIAS
                float so = 1.0f / (1.0f + expf(-go));
                float cn = creg[j] * sf + si * tanhf(gj);
                creg[j] = cn;
                float hv = tanhf(cn) * so;

                int gidx = row * HID + hb * 8 + j;
                if (t < SEQ - 1) {
                    __nv_bfloat16 hh = __float2bfloat16(hv);
                    hd_hi[gidx] = hh;
                    hd_lo[gidx] = __float2bfloat16(hv - __bfloat162float(hh));
                } else {
                    out[gidx] = hv;
                    out[BATCH * HID + gidx] = cn;
                }
            }
        }
        __syncthreads();

        // ---- grid-wide barrier ----
        if (tid == 0) {
            __threadfence();
            unsigned gen = *((volatile unsigned*)&g_bar_gen);
            unsigned arr = atomicAdd(&g_bar_cnt, 1);
            if (arr == NCTA - 1) {
                atomicExch(&g_bar_cnt, 0);
                __threadfence();
                atomicAdd(&g_bar_gen, 1);
            } else {
                while (*((volatile unsigned*)&g_bar_gen) == gen) __nanosleep(40);
            }
        }
        __syncthreads();
    }
}

// ---------------------------------------------------------------------------
extern "C" void kernel_launch(void* const* d_in, const int* in_sizes, int n_in,
                              void* d_out, int out_size) {
    const float* x  = (const float*)d_in[0];
    const float* h0 = (const float*)d_in[1];
    const float* c0 = (const float*)d_in[2];
    const float* Wx = (const float*)d_in[3];
    const float* Wh = (const float*)d_in[4];
    const float* bh = (const float*)d_in[5];
    float* out = (float*)d_out;

    cudaFuncSetAttribute(lstm_persist, cudaFuncAttributeMaxDynamicSharedMemorySize, SM_TOTAL);

    split_wh<<<GATES, 256>>>(Wh);
    split_h0<<<64, 1024>>>(h0);
    gx_gemm<<<dim3(GATES / 64, (SEQ * BATCH) / 64), 256>>>(x, Wx);
    lstm_persist<<<NCTA, NTHR, SM_TOTAL>>>(c0, bh, out);
}

// round 6
// speedup vs baseline: 2.9612x; 1.2694x over previous
#include <cuda_runtime.h>
#include <cuda_bf16.h>
#include <math.h>
#include <stdint.h>

#define SEQ    512
#define BATCH  64
#define DIM    512
#define HID    1024
#define GATES  4096
#define NCTA   128
#define NTHR   256

// ---------------------------------------------------------------------------
// Device scratch (allocation-free rule)
// ---------------------------------------------------------------------------
__device__ float          g_gx[(size_t)SEQ * BATCH * GATES];   // input projection (fp32)
__device__ __nv_bfloat16  g_xh[(size_t)SEQ * BATCH * DIM];     // x split hi  [m][k]
__device__ __nv_bfloat16  g_xl[(size_t)SEQ * BATCH * DIM];     // x split lo
__device__ __nv_bfloat16  g_wxt_hi[(size_t)GATES * DIM];       // WxT split hi [n][k]
__device__ __nv_bfloat16  g_wxt_lo[(size_t)GATES * DIM];       // WxT split lo
__device__ __nv_bfloat16  g_wt_hi[(size_t)GATES * HID];        // WhT split hi [n][k]
__device__ __nv_bfloat16  g_wt_lo[(size_t)GATES * HID];        // WhT split lo
__device__ __nv_bfloat16  g_h_hi[2][BATCH * HID];              // ping-pong hidden, hi
__device__ __nv_bfloat16  g_h_lo[2][BATCH * HID];              // ping-pong hidden, lo
__device__ unsigned       g_bar_cnt;
__device__ unsigned       g_bar_gen;

// ---------------------------------------------------------------------------
// PTX helpers (portable sm_80+ tensor path: ldmatrix + mma.sync + cp.async)
// ---------------------------------------------------------------------------
__device__ __forceinline__ uint32_t smem_u32(const void* p) {
    uint32_t a;
    asm("{ .reg .u64 t; cvta.to.shared.u64 t, %1; cvt.u32.u64 %0, t; }" : "=r"(a) : "l"(p));
    return a;
}

#define LDSM_X4(r0, r1, r2, r3, addr) \
    asm volatile("ldmatrix.sync.aligned.m8n8.x4.shared.b16 {%0,%1,%2,%3}, [%4];" \
                 : "=r"(r0), "=r"(r1), "=r"(r2), "=r"(r3) : "r"(addr))

#define MMA16816(c, a0, a1, a2, a3, b0, b1) \
    asm volatile("mma.sync.aligned.m16n8k16.row.col.f32.bf16.bf16.f32 " \
                 "{%0,%1,%2,%3}, {%4,%5,%6,%7}, {%8,%9}, {%0,%1,%2,%3};" \
                 : "+f"((c)[0]), "+f"((c)[1]), "+f"((c)[2]), "+f"((c)[3]) \
                 : "r"(a0), "r"(a1), "r"(a2), "r"(a3), "r"(b0), "r"(b1))

__device__ __forceinline__ void cpa16(uint32_t dst, const void* src) {
    asm volatile("cp.async.cg.shared.global [%0], [%1], 16;" :: "r"(dst), "l"(src));
}
#define CPA_COMMIT() asm volatile("cp.async.commit_group;" ::: "memory")
#define CPA_WAIT(n)  asm volatile("cp.async.wait_group %0;" :: "n"(n) : "memory")

// ---------------------------------------------------------------------------
// Split kernels
// ---------------------------------------------------------------------------
__global__ void split_x(const float* __restrict__ x) {
    size_t i = (size_t)blockIdx.x * blockDim.x + threadIdx.x;
    if (i < (size_t)SEQ * BATCH * DIM) {
        float v = x[i];
        __nv_bfloat16 hh = __float2bfloat16(v);
        g_xh[i] = hh;
        g_xl[i] = __float2bfloat16(v - __bfloat162float(hh));
    }
}

__global__ void split_wxt(const float* __restrict__ Wx) {
    int n = blockIdx.x;                 // 0..4095
    int k = threadIdx.x;                // 0..511
    float w = Wx[(size_t)k * GATES + n];
    __nv_bfloat16 hh = __float2bfloat16(w);
    g_wxt_hi[(size_t)n * DIM + k] = hh;
    g_wxt_lo[(size_t)n * DIM + k] = __float2bfloat16(w - __bfloat162float(hh));
}

__global__ void split_wh(const float* __restrict__ Wh) {
    int n = blockIdx.x;  // gate column 0..4095
    for (int k = threadIdx.x; k < HID; k += blockDim.x) {
        float w = Wh[(size_t)k * GATES + n];
        __nv_bfloat16 hh = __float2bfloat16(w);
        g_wt_hi[(size_t)n * HID + k] = hh;
        g_wt_lo[(size_t)n * HID + k] = __float2bfloat16(w - __bfloat162float(hh));
    }
}

__global__ void split_h0(const float* __restrict__ h0) {
    int i = blockIdx.x * blockDim.x + threadIdx.x;
    if (i < BATCH * HID) {
        float v = h0[i];
        __nv_bfloat16 hh = __float2bfloat16(v);
        g_h_hi[0][i] = hh;
        g_h_lo[0][i] = __float2bfloat16(v - __bfloat162float(hh));
    }
}

// ---------------------------------------------------------------------------
// gx = x @ Wx via bf16 hi/lo 3-pass mma.sync.
// C[32768, 4096], K=512. Block tile 128x128, 8 warps (2m x 4n), warp 64x32.
// K-chunk 32, double-buffered cp.async.
// SMEM rows: 32 k bf16 = 64 B + 16 pad = 80 B stride (16B aligned, conflict-free).
// ---------------------------------------------------------------------------
#define GA_STR   80u
#define GS_AHI   0u
#define GS_ALO   10240u
#define GS_BHI   20480u
#define GS_BLO   30720u
#define GS_STAGE 40960u
#define GS_TOTAL 81920u

__global__ void __launch_bounds__(256, 1)
gx_mma(float* __restrict__ dummy) {
    extern __shared__ char sm[];
    const uint32_t sb = smem_u32(sm);

    const int tid = threadIdx.x;
    const int wid = tid >> 5;
    const int lid = tid & 31;
    const int wm = wid >> 2;            // 0..1
    const int wn = wid & 3;             // 0..3
    const int bm = blockIdx.y * 128;
    const int bn = blockIdx.x * 128;

    // lane addressing (same fragment pattern as validated recurrence kernel)
    const uint32_t a_lane = (uint32_t)(wm * 64 + (lid & 15)) * GA_STR + (uint32_t)(lid >> 4) * 16u;
    const uint32_t b_lane = (uint32_t)(wn * 32 + (lid & 7) + ((lid >> 4) << 3)) * GA_STR
                          + (uint32_t)((lid >> 3) & 1) * 16u;

    // prologue: chunk 0
    {
        #pragma unroll
        for (int i = 0; i < 2; i++) {
            int e = tid + i * 256;              // 0..511
            int r = e >> 2, u = e & 3;
            uint32_t du = (uint32_t)r * GA_STR + (uint32_t)u * 16u;
            cpa16(sb + GS_AHI + du, g_xh + (size_t)(bm + r) * DIM + u * 8);
            cpa16(sb + GS_ALO + du, g_xl + (size_t)(bm + r) * DIM + u * 8);
            cpa16(sb + GS_BHI + du, g_wxt_hi + (size_t)(bn + r) * DIM + u * 8);
            cpa16(sb + GS_BLO + du, g_wxt_lo + (size_t)(bn + r) * DIM + u * 8);
        }
        CPA_COMMIT();
    }

    float acc[64] = {};   // [mt 0..3][j 0..3][4]

    #pragma unroll 1
    for (int c = 0; c < 16; c++) {
        if (c < 15) {
            uint32_t stg = (uint32_t)((c + 1) & 1) * GS_STAGE;
            int kc = (c + 1) * 32;
            #pragma unroll
            for (int i = 0; i < 2; i++) {
                int e = tid + i * 256;
                int r = e >> 2, u = e & 3;
                uint32_t du = stg + (uint32_t)r * GA_STR + (uint32_t)u * 16u;
                cpa16(sb + GS_AHI + du, g_xh + (size_t)(bm + r) * DIM + kc + u * 8);
                cpa16(sb + GS_ALO + du, g_xl + (size_t)(bm + r) * DIM + kc + u * 8);
                cpa16(sb + GS_BHI + du, g_wxt_hi + (size_t)(bn + r) * DIM + kc + u * 8);
                cpa16(sb + GS_BLO + du, g_wxt_lo + (size_t)(bn + r) * DIM + kc + u * 8);
            }
            CPA_COMMIT();
            CPA_WAIT(1);
        } else {
            CPA_WAIT(0);
        }
        __syncthreads();

        const uint32_t stg = (uint32_t)(c & 1) * GS_STAGE;
        const uint32_t abase = sb + stg + a_lane;
        const uint32_t bbase = sb + stg + b_lane;

        #pragma unroll
        for (int kk = 0; kk < 2; kk++) {
            // B fragments: 2 n16 tiles, hi + lo
            uint32_t bhf[8], blf[8];
            #pragma unroll
            for (int bt = 0; bt < 2; bt++) {
                LDSM_X4(bhf[bt * 4], bhf[bt * 4 + 1], bhf[bt * 4 + 2], bhf[bt * 4 + 3],
                        bbase + GS_BHI + (uint32_t)bt * (16u * GA_STR) + kk * 32u);
                LDSM_X4(blf[bt * 4], blf[bt * 4 + 1], blf[bt * 4 + 2], blf[bt * 4 + 3],
                        bbase + GS_BLO + (uint32_t)bt * (16u * GA_STR) + kk * 32u);
            }
            #pragma unroll
            for (int mt = 0; mt < 4; mt++) {
                uint32_t ah0, ah1, ah2, ah3, al0, al1, al2, al3;
                uint32_t ao = (uint32_t)mt * (16u * GA_STR) + kk * 32u;
                LDSM_X4(ah0, ah1, ah2, ah3, abase + GS_AHI + ao);
                LDSM_X4(al0, al1, al2, al3, abase + GS_ALO + ao);
                #pragma unroll
                for (int j = 0; j < 4; j++) {
                    float* a = acc + (mt * 4 + j) * 4;
                    uint32_t b0 = (j & 1) ? bhf[(j >> 1) * 4 + 2] : bhf[(j >> 1) * 4 + 0];
                    uint32_t b1 = (j & 1) ? bhf[(j >> 1) * 4 + 3] : bhf[(j >> 1) * 4 + 1];
                    uint32_t c0 = (j & 1) ? blf[(j >> 1) * 4 + 2] : blf[(j >> 1) * 4 + 0];
                    uint32_t c1 = (j & 1) ? blf[(j >> 1) * 4 + 3] : blf[(j >> 1) * 4 + 1];
                    MMA16816(a, ah0, ah1, ah2, ah3, b0, b1);
                    MMA16816(a, ah0, ah1, ah2, ah3, c0, c1);
                    MMA16816(a, al0, al1, al2, al3, b0, b1);
                }
            }
        }
        __syncthreads();
    }

    // epilogue: direct fp32 stores to g_gx
    #pragma unroll
    for (int mt = 0; mt < 4; mt++) {
        int r0 = bm + wm * 64 + mt * 16 + (lid >> 2);
        #pragma unroll
        for (int j = 0; j < 4; j++) {
            const float* a = acc + (mt * 4 + j) * 4;
            int col = bn + wn * 32 + j * 8 + (lid & 3) * 2;
            *reinterpret_cast<float2*>(&g_gx[(size_t)r0 * GATES + col]) = make_float2(a[0], a[1]);
            *reinterpret_cast<float2*>(&g_gx[(size_t)(r0 + 8) * GATES + col]) = make_float2(a[2], a[3]);
        }
    }
}

// ---------------------------------------------------------------------------
// SMEM layout for recurrence (unchanged, validated)
// ---------------------------------------------------------------------------
#define BSTR     2064u
#define ASTR     272u
#define SM_BHI   0u
#define SM_BLO   66048u
#define SM_A     132096u
#define A_STAGE  34816u
#define A_LO     17408u
#define SM_GX    201728u
#define GXSTR    144u
#define SM_SG    210944u
#define SM_BIAS  219648u
#define SM_TOTAL 219776u

// ---------------------------------------------------------------------------
// Persistent LSTM recurrence (byte-identical to round-5 passing version)
// ---------------------------------------------------------------------------
__global__ void __launch_bounds__(NTHR, 1)
lstm_persist(const float* __restrict__ c0, const float* __restrict__ bh,
             float* __restrict__ out) {
    extern __shared__ char sm[];
    const uint32_t sb = smem_u32(sm);

    const int tid = threadIdx.x;
    const int wid = tid >> 5;
    const int lid = tid & 31;
    const int hb  = blockIdx.x;

    for (int idx = tid; idx < 32 * 128; idx += NTHR) {
        int n = idx >> 7, u = idx & 127;
        int gr = (n >> 3) * HID + hb * 8 + (n & 7);
        uint32_t dst = n * BSTR + u * 16u;
        *reinterpret_cast<uint4*>(sm + SM_BHI + dst) =
            *reinterpret_cast<const uint4*>(g_wt_hi + (size_t)gr * HID + u * 8);
        *reinterpret_cast<uint4*>(sm + SM_BLO + dst) =
            *reinterpret_cast<const uint4*>(g_wt_lo + (size_t)gr * HID + u * 8);
    }

    if (tid < 32) {
        int gc = (tid >> 3) * HID + hb * 8 + (tid & 7);
        *reinterpret_cast<float*>(sm + SM_BIAS + tid * 4) = bh[gc];
    }

    const int row = wid * 32 + lid;
    float creg[8];
    if (wid < 2) {
        #pragma unroll
        for (int j = 0; j < 8; j++) creg[j] = c0[row * HID + hb * 8 + j];
    }
    __syncthreads();

    const int mt = wid & 3;
    const int nh = wid >> 2;
    const uint32_t a_lane = (uint32_t)(mt * 16 + (lid & 15)) * ASTR + (uint32_t)(lid >> 4) * 16u;
    const uint32_t b_lane = (uint32_t)(nh * 16 + (lid & 7) + ((lid >> 4) << 3)) * BSTR
                          + (uint32_t)((lid >> 3) & 1) * 16u;
    const float* bsm = reinterpret_cast<const float*>(sm + SM_BIAS);

    for (int t = 0; t < SEQ; t++) {
        const __nv_bfloat16* hs_hi = g_h_hi[t & 1];
        const __nv_bfloat16* hs_lo = g_h_lo[t & 1];

        {
            #pragma unroll
            for (int i = 0; i < 4; i++) {
                int e = tid + i * NTHR;
                int r = e >> 4, u = e & 15;
                uint32_t dst = SM_A + (uint32_t)r * ASTR + (uint32_t)u * 16u;
                cpa16(sb + dst,        hs_hi + r * HID + u * 8);
                cpa16(sb + dst + A_LO, hs_lo + r * HID + u * 8);
            }
            #pragma unroll
            for (int i = 0; i < 2; i++) {
                int e = tid + i * NTHR;
                int r = e >> 3, u = e & 7;
                const float* src = g_gx + ((size_t)t * BATCH + r) * GATES
                                 + (u >> 1) * HID + hb * 8 + (u & 1) * 4;
                cpa16(sb + SM_GX + (uint32_t)r * GXSTR + (uint32_t)u * 16u, src);
            }
            CPA_COMMIT();
        }

        float acc[8] = {};

        #pragma unroll 1
        for (int c = 0; c < 8; c++) {
            if (c < 7) {
                uint32_t stg = SM_A + (uint32_t)((c + 1) & 1) * A_STAGE;
                int kc = (c + 1) * 128;
                #pragma unroll
                for (int i = 0; i < 4; i++) {
                    int e = tid + i * NTHR;
                    int r = e >> 4, u = e & 15;
                    uint32_t dst = stg + (uint32_t)r * ASTR + (uint32_t)u * 16u;
                    cpa16(sb + dst,        hs_hi + r * HID + kc + u * 8);
                    cpa16(sb + dst + A_LO, hs_lo + r * HID + kc + u * 8);
                }
                CPA_COMMIT();
                CPA_WAIT(1);
            } else {
                CPA_WAIT(0);
            }
            __syncthreads();

            const uint32_t a_hi = sb + SM_A + (uint32_t)(c & 1) * A_STAGE + a_lane;
            const uint32_t a_lo = a_hi + A_LO;
            const uint32_t b_hi = sb + SM_BHI + b_lane + (uint32_t)c * 256u;
            const uint32_t b_lo = b_hi + (SM_BLO - SM_BHI);

            #pragma unroll
            for (int kk = 0; kk < 8; kk++) {
                uint32_t ah0, ah1, ah2, ah3, al0, al1, al2, al3;
                uint32_t bh0, bh1, bh2, bh3, bl0, bl1, bl2, bl3;
                LDSM_X4(ah0, ah1, ah2, ah3, a_hi + kk * 32u);
                LDSM_X4(bh0, bh1, bh2, bh3, b_hi + kk * 32u);
                LDSM_X4(al0, al1, al2, al3, a_lo + kk * 32u);
                LDSM_X4(bl0, bl1, bl2, bl3, b_lo + kk * 32u);

                MMA16816(acc,     ah0, ah1, ah2, ah3, bh0, bh1);
                MMA16816(acc + 4, ah0, ah1, ah2, ah3, bh2, bh3);
                MMA16816(acc,     ah0, ah1, ah2, ah3, bl0, bl1);
                MMA16816(acc + 4, ah0, ah1, ah2, ah3, bl2, bl3);
                MMA16816(acc,     al0, al1, al2, al3, bh0, bh1);
                MMA16816(acc + 4, al0, al1, al2, al3, bh2, bh3);
            }
            __syncthreads();
        }

        {
            float* sg = reinterpret_cast<float*>(sm + SM_SG);
            int r0 = mt * 16 + (lid >> 2);
            int cb = nh * 16 + (lid & 3) * 2;
            #pragma unroll
            for (int ng = 0; ng < 2; ng++) {
                float* p0 = sg + (size_t)r0 * 34 + cb + ng * 8;
                float* p1 = sg + (size_t)(r0 + 8) * 34 + cb + ng * 8;
                p0[0] = acc[ng * 4 + 0]; p0[1] = acc[ng * 4 + 1];
                p1[0] = acc[ng * 4 + 2]; p1[1] = acc[ng * 4 + 3];
            }
        }
        __syncthreads();

        if (wid < 2) {
            const float* sg    = reinterpret_cast<const float*>(sm + SM_SG) + (size_t)row * 34;
            const float* gxrow = reinterpret_cast<const float*>(sm + SM_GX + (uint32_t)row * GXSTR);
            __nv_bfloat16* hd_hi = g_h_hi[(t + 1) & 1];
            __nv_bfloat16* hd_lo = g_h_lo[(t + 1) & 1];

            #pragma unroll
            for (int j = 0; j < 8; j++) {
                float gi = sg[j]      + gxrow[j]      + bsm[j];
                float gf = sg[8 + j]  + gxrow[8 + j]  + bsm[8 + j];
                float gj = sg[16 + j] + gxrow[16 + j] + bsm[16 + j];
                float go = sg[24 + j] + gxrow[24 + j] + bsm[24 + j];

                float si = 1.0f / (1.0f + expf(-gi));
                float sf = 1.0f / (1.0f + expf(-(gf + 1.0f)));
                float so = 1.0f / (1.0f + expf(-go));
                float cn = creg[j] * sf + si * tanhf(gj);
                creg[j] = cn;
                float hv = tanhf(cn) * so;

                int gidx = row * HID + hb * 8 + j;
                if (t < SEQ - 1) {
                    __nv_bfloat16 hh = __float2bfloat16(hv);
                    hd_hi[gidx] = hh;
                    hd_lo[gidx] = __float2bfloat16(hv - __bfloat162float(hh));
                } else {
                    out[gidx] = hv;
                    out[BATCH * HID + gidx] = cn;
                }
            }
        }
        __syncthreads();

        if (tid == 0) {
            __threadfence();
            unsigned gen = *((volatile unsigned*)&g_bar_gen);
            unsigned arr = atomicAdd(&g_bar_cnt, 1);
            if (arr == NCTA - 1) {
                atomicExch(&g_bar_cnt, 0);
                __threadfence();
                atomicAdd(&g_bar_gen, 1);
            } else {
                while (*((volatile unsigned*)&g_bar_gen) == gen) __nanosleep(40);
            }
        }
        __syncthreads();
    }
}

// ---------------------------------------------------------------------------
extern "C" void kernel_launch(void* const* d_in, const int* in_sizes, int n_in,
                              void* d_out, int out_size) {
    const float* x  = (const float*)d_in[0];
    const float* h0 = (const float*)d_in[1];
    const float* c0 = (const float*)d_in[2];
    const float* Wx = (const float*)d_in[3];
    const float* Wh = (const float*)d_in[4];
    const float* bh = (const float*)d_in[5];
    float* out = (float*)d_out;

    cudaFuncSetAttribute(gx_mma, cudaFuncAttributeMaxDynamicSharedMemorySize, GS_TOTAL);
    cudaFuncSetAttribute(lstm_persist, cudaFuncAttributeMaxDynamicSharedMemorySize, SM_TOTAL);

    split_x<<<(SEQ * BATCH * DIM + 255) / 256, 256>>>(x);
    split_wxt<<<GATES, DIM>>>(Wx);
    split_wh<<<GATES, 256>>>(Wh);
    split_h0<<<64, 1024>>>(h0);
    gx_mma<<<dim3(GATES / 128, (SEQ * BATCH) / 128), 256, GS_TOTAL>>>(nullptr);
    lstm_persist<<<NCTA, NTHR, SM_TOTAL>>>(c0, bh, out);
}